// round 2
// baseline (speedup 1.0000x reference)
#include <cuda_runtime.h>
#include <math.h>

#define NB 32
#define NT 512
#define NI 1024
#define NH 1024
#define NG 4096                 // 4 gates * H
#define GB (NG*NB)              // gate elements per step, layout [j][b]
#define LOFF (4*NH*NI)          // layer stride in Wh / Wx (floats)
#define GRID_BLOCKS 96

// ---------------- device scratch (no allocations allowed) -------------------
__device__ float g_xg0[(size_t)NT * GB];   // [t][j][b]  Wx0 @ x_t, then += Wh0@h0
__device__ float g_g1a[GB];                // Wh1 @ h1
__device__ float g_g1b[GB];                // Wx1 @ h0
__device__ float g_hcat[NB * 2048];        // [b][0..1023]=h1, [b][1024..2047]=h0
__device__ float g_c0[NB * NH];            // [hh][b]
__device__ float g_c1[NB * NH];            // [hh][b]
__device__ unsigned g_bar_count;
__device__ unsigned g_bar_gen;

// ---------------------------------------------------------------------------
__global__ void init_state() {
    int i = blockIdx.x * blockDim.x + threadIdx.x;
    int n = gridDim.x * blockDim.x;
    for (int k = i; k < NB * 2048; k += n) g_hcat[k] = 0.0f;
    for (int k = i; k < NB * NH; k += n) { g_c0[k] = 0.0f; g_c1[k] = 0.0f; }
    if (i == 0) { g_bar_count = 0; g_bar_gen = 0; }
}

// ---------------------------------------------------------------------------
// Precompute xg0[t][j][b] = sum_d Wx[0][j][d] * seq[b][t][d]
// M=4096, N=16384 (c = t*32+b), K=1024. 128x64x16 tile, 256 thr, 8x4 micro.
// ---------------------------------------------------------------------------
__global__ __launch_bounds__(256) void pregemm(const float* __restrict__ Wx,
                                               const float* __restrict__ seq) {
    __shared__ __align__(16) float As[16][132];
    __shared__ __align__(16) float Bs[64][20];

    int tid = threadIdx.x;
    int j0 = blockIdx.y * 128;
    int c0 = blockIdx.x * 64;

    float acc[8][4];
#pragma unroll
    for (int m = 0; m < 8; m++)
#pragma unroll
        for (int n = 0; n < 4; n++) acc[m][n] = 0.0f;

    int m0 = (tid & 15) * 8;
    int n0 = (tid >> 4) * 4;

    int cl = tid >> 2;
    int bkg = tid & 3;
    int c = c0 + cl;
    int bb_ld = c & 31;
    int tt_ld = c >> 5;
    const float* Bcol = seq + ((size_t)bb_ld * NT + tt_ld) * NI + bkg * 4;

    for (int kt = 0; kt < NI / 16; kt++) {
        int k0 = kt * 16;
#pragma unroll
        for (int i = 0; i < 2; i++) {
            int flat = tid + i * 256;
            int row = flat >> 2;
            int akg = flat & 3;
            float4 v = *(const float4*)(Wx + (size_t)(j0 + row) * NI + k0 + akg * 4);
            As[akg * 4 + 0][row] = v.x;
            As[akg * 4 + 1][row] = v.y;
            As[akg * 4 + 2][row] = v.z;
            As[akg * 4 + 3][row] = v.w;
        }
        {
            float4 v = *(const float4*)(Bcol + k0);
            *(float4*)&Bs[cl][bkg * 4] = v;
        }
        __syncthreads();
#pragma unroll
        for (int k = 0; k < 16; k++) {
            float4 a0 = *(float4*)&As[k][m0];
            float4 a1 = *(float4*)&As[k][m0 + 4];
            float av[8] = {a0.x, a0.y, a0.z, a0.w, a1.x, a1.y, a1.z, a1.w};
            float bv[4];
#pragma unroll
            for (int n = 0; n < 4; n++) bv[n] = Bs[n0 + n][k];
#pragma unroll
            for (int m = 0; m < 8; m++) {
                acc[m][0] += av[m] * bv[0];
                acc[m][1] += av[m] * bv[1];
                acc[m][2] += av[m] * bv[2];
                acc[m][3] += av[m] * bv[3];
            }
        }
        __syncthreads();
    }
    int cc = c0 + n0;
    int tt = cc >> 5;
    int bb = cc & 31;
    float* outp = g_xg0 + (size_t)tt * GB + bb;
#pragma unroll
    for (int m = 0; m < 8; m++) {
        int j = j0 + m0 + m;
        *(float4*)(outp + (size_t)j * 32) =
            make_float4(acc[m][0], acc[m][1], acc[m][2], acc[m][3]);
    }
}

// ---------------------------------------------------------------------------
// packed fp32x2 FMA (sm_100+): d.lo += a.lo*b.lo ; d.hi += a.hi*b.hi
// ---------------------------------------------------------------------------
__device__ __forceinline__ void ffma2(unsigned long long& d,
                                      unsigned long long a,
                                      unsigned long long b) {
    asm("fma.rn.f32x2 %0, %1, %2, %0;" : "+l"(d) : "l"(a), "l"(b));
}

union F2 { unsigned long long u; float2 f; };

__device__ __forceinline__ float sigf(float x) {
    return 1.0f / (1.0f + __expf(-x));
}
__device__ __forceinline__ float tanhfast(float x) {
    return 2.0f / (1.0f + __expf(-2.0f * x)) - 1.0f;
}

// ---------------------------------------------------------------------------
// software grid barrier (96 co-resident blocks)
// ---------------------------------------------------------------------------
__device__ __forceinline__ void grid_sync(unsigned& gen) {
    __syncthreads();
    if (threadIdx.x == 0) {
        unsigned target = gen + 1;
        __threadfence();
        unsigned arrived = atomicAdd(&g_bar_count, 1u);
        if (arrived == GRID_BLOCKS - 1) {
            atomicExch(&g_bar_count, 0u);
            __threadfence();
            atomicExch(&g_bar_gen, target);
        } else {
            while (*(volatile unsigned*)&g_bar_gen < target) {}
            __threadfence();
        }
        gen = target;
    }
    __syncthreads();
}

// ---------------------------------------------------------------------------
// Cell updates for one pipelined step.
//   t >= 0   : layer-1 update for step t (gates = g1a + g1b + bias1)
//   t < NT-1 : layer-0 update for step t+1 (gates = xg0[t+1] + bias0)
// ---------------------------------------------------------------------------
__device__ void do_update(int t, const float* __restrict__ Bias,
                          float* __restrict__ out) {
    for (int e = blockIdx.x * 256 + threadIdx.x; e < 2 * NB * NH;
         e += GRID_BLOCKS * 256) {
        int e2 = e & 32767;
        int b = e2 & 31;
        int hh = e2 >> 5;
        int gidx = hh * 32 + b;
        if (e < 32768) {                       // layer 1, step t
            if (t < 0) continue;
            float f = g_g1a[gidx]          + g_g1b[gidx]          + Bias[4096 + hh];
            float w = g_g1a[gidx + 32768]  + g_g1b[gidx + 32768]  + Bias[5120 + hh];
            float i_= g_g1a[gidx + 65536]  + g_g1b[gidx + 65536]  + Bias[6144 + hh];
            float o = g_g1a[gidx + 98304]  + g_g1b[gidx + 98304]  + Bias[7168 + hh];
            float cv = g_c1[gidx];
            float cn = cv * sigf(f) + sigf(w) * tanhfast(i_);
            float hn = tanhfast(cn) * sigf(o);
            g_c1[gidx] = cn;
            g_hcat[b * 2048 + hh] = hn;        // h1
            if (t == NT - 1) out[b * 1024 + hh] = hn;
        } else {                               // layer 0, step t+1
            if (t >= NT - 1) continue;
            const float* gg = g_xg0 + (size_t)(t + 1) * GB;
            float f = gg[gidx]          + Bias[hh];
            float w = gg[gidx + 32768]  + Bias[1024 + hh];
            float i_= gg[gidx + 65536]  + Bias[2048 + hh];
            float o = gg[gidx + 98304]  + Bias[3072 + hh];
            float cv = g_c0[gidx];
            float cn = cv * sigf(f) + sigf(w) * tanhfast(i_);
            float hn = tanhfast(cn) * sigf(o);
            g_c0[gidx] = cn;
            g_hcat[b * 2048 + 1024 + hh] = hn; // h0
        }
    }
}

// ---------------------------------------------------------------------------
// Persistent LSTM kernel. 96 blocks:
//   region0 (bid  0..31): Wh0 @ h0  -> xg0[t+1] +=      (gates for layer0, t+1)
//   region1 (bid 32..63): Wh1 @ h1  -> g1a               (layer1, t)
//   region2 (bid 64..95): Wx1 @ h0  -> g1b               (layer1, t)
// Each block: 128 rows x 32 cols, K=1024, fp32x2 packed FMA.
// ---------------------------------------------------------------------------
__global__ __launch_bounds__(256, 1) void lstm_persist(
    const float* __restrict__ Wh, const float* __restrict__ Wx,
    const float* __restrict__ Bias, float* __restrict__ out) {
    __shared__ __align__(16) float Ws[32][132];            // [k][m]
    __shared__ unsigned long long hs2[32][33];             // [b][k], lane-dup

    unsigned gen = 0;
    int tid = threadIdx.x;
    int bid = blockIdx.x;
    int region = bid >> 5;
    int j0 = (bid & 31) * 128;

    const float* Wbase = (region == 0) ? Wh
                       : (region == 1) ? (Wh + LOFF)
                                       : (Wx + LOFF);
    const float* hvec = (region == 1) ? g_hcat : (g_hcat + 1024);

    int m0 = (tid >> 4) * 8;       // 8 rows (4 packed float2)
    int n0 = (tid & 15) * 2;       // 2 cols

    // prologue: layer-0 update for t=0 (gates = xg0[0] + bias, h=c=0)
    do_update(-1, Bias, out);
    grid_sync(gen);

    for (int t = 0; t < NT; t++) {
        if (!(region == 0 && t == NT - 1)) {
            unsigned long long acc[8];
#pragma unroll
            for (int i = 0; i < 8; i++) acc[i] = 0ull;

            for (int kt = 0; kt < 32; kt++) {
                int k0 = kt * 32;
#pragma unroll
                for (int i = 0; i < 4; i++) {
                    int flat = tid + i * 256;
                    int row = flat >> 3;
                    int wkg = flat & 7;
                    float4 v = *(const float4*)(Wbase +
                        (size_t)(j0 + row) * NI + k0 + wkg * 4);
                    Ws[wkg * 4 + 0][row] = v.x;
                    Ws[wkg * 4 + 1][row] = v.y;
                    Ws[wkg * 4 + 2][row] = v.z;
                    Ws[wkg * 4 + 3][row] = v.w;
                }
                {
                    int b = tid >> 3;
                    int kg = tid & 7;
                    float4 v = *(const float4*)(hvec + b * 2048 + k0 + kg * 4);
                    F2 d0, d1, d2, d3;
                    d0.f = make_float2(v.x, v.x);
                    d1.f = make_float2(v.y, v.y);
                    d2.f = make_float2(v.z, v.z);
                    d3.f = make_float2(v.w, v.w);
                    hs2[b][kg * 4 + 0] = d0.u;
                    hs2[b][kg * 4 + 1] = d1.u;
                    hs2[b][kg * 4 + 2] = d2.u;
                    hs2[b][kg * 4 + 3] = d3.u;
                }
                __syncthreads();
#pragma unroll
                for (int k = 0; k < 32; k++) {
                    ulonglong2 a01 = *(const ulonglong2*)&Ws[k][m0];
                    ulonglong2 a23 = *(const ulonglong2*)&Ws[k][m0 + 4];
                    unsigned long long b0 = hs2[n0][k];
                    unsigned long long b1 = hs2[n0 + 1][k];
                    ffma2(acc[0], a01.x, b0); ffma2(acc[1], a01.x, b1);
                    ffma2(acc[2], a01.y, b0); ffma2(acc[3], a01.y, b1);
                    ffma2(acc[4], a23.x, b0); ffma2(acc[5], a23.x, b1);
                    ffma2(acc[6], a23.y, b0); ffma2(acc[7], a23.y, b1);
                }
                __syncthreads();
            }
            // epilogue
            if (region == 0) {
                float* g0 = g_xg0 + (size_t)(t + 1) * GB;
#pragma unroll
                for (int m2 = 0; m2 < 4; m2++) {
                    F2 ca, cb;
                    ca.u = acc[m2 * 2 + 0];    // col n0  : .x row even, .y row odd
                    cb.u = acc[m2 * 2 + 1];    // col n0+1
                    size_t r0 = (size_t)(j0 + m0 + 2 * m2) * 32 + n0;
                    float2* p0 = (float2*)(g0 + r0);
                    float2* p1 = (float2*)(g0 + r0 + 32);
                    float2 v0 = *p0, v1 = *p1;
                    *p0 = make_float2(v0.x + ca.f.x, v0.y + cb.f.x);
                    *p1 = make_float2(v1.x + ca.f.y, v1.y + cb.f.y);
                }
            } else {
                float* gout = (region == 1) ? g_g1a : g_g1b;
#pragma unroll
                for (int m2 = 0; m2 < 4; m2++) {
                    F2 ca, cb;
                    ca.u = acc[m2 * 2 + 0];
                    cb.u = acc[m2 * 2 + 1];
                    size_t r0 = (size_t)(j0 + m0 + 2 * m2) * 32 + n0;
                    *(float2*)(gout + r0)      = make_float2(ca.f.x, cb.f.x);
                    *(float2*)(gout + r0 + 32) = make_float2(ca.f.y, cb.f.y);
                }
            }
        }
        grid_sync(gen);
        do_update(t, Bias, out);
        if (t < NT - 1) grid_sync(gen);
    }
}

// ---------------------------------------------------------------------------
extern "C" void kernel_launch(void* const* d_in, const int* in_sizes, int n_in,
                              void* d_out, int out_size) {
    const float* seq  = (const float*)d_in[0];  // (32, 512, 1024)
    const float* Wh   = (const float*)d_in[1];  // (2, 4, 1024, 1024)
    const float* Wx   = (const float*)d_in[2];  // (2, 4, 1024, 1024)
    const float* Bias = (const float*)d_in[3];  // (2, 4, 1024)
    float* out = (float*)d_out;                 // (32, 1024)

    init_state<<<64, 256>>>();
    pregemm<<<dim3(NT * NB / 64, NG / 128), 256>>>(Wx, seq);
    lstm_persist<<<GRID_BLOCKS, 256>>>(Wh, Wx, Bias, out);
}

// round 4
// speedup vs baseline: 2.6191x; 2.6191x over previous
#include <cuda_runtime.h>
#include <cuda_bf16.h>
#include <math.h>
#include <stdint.h>

#define NB 32
#define NT 512
#define NI 1024
#define NH 1024
#define NG 4096
#define GB (NG*NB)              // gate elems per step, layout [j][b]
#define LOFF (4*NH*NI)
#define GRID_BLOCKS 96
#define NK16 64                 // K=1024 in 64 chunks of 16
#define B_B32 16384             // one B operand (hi or lo) in b32 units: 64*4*32*2
#define SMEM_BYTES (2 * B_B32 * 4)   // 128 KB: Bhi + Blo

// ---------------- device scratch -------------------------------------------
__device__ __align__(256) float g_xg0[(size_t)(NT + 1) * GB]; // [t][j][b]
__device__ __align__(256) float g_g1a[GB];
__device__ __align__(256) float g_g1b[GB];
__device__ float g_c0[NB * NH];
__device__ float g_c1[NB * NH];
// A operands in m16n8k16 fragment layout: [region*32+blk][warp][k16][lane][4 b32]
__device__ __align__(128) __nv_bfloat16 g_Ahi[(size_t)3 * 4096 * 1024];
__device__ __align__(128) __nv_bfloat16 g_Alo[(size_t)3 * 4096 * 1024];
// B operands in fragment layout: [k16][n8][lane][2 b32]
__device__ __align__(128) uint32_t g_B0hi[B_B32];
__device__ __align__(128) uint32_t g_B0lo[B_B32];
__device__ __align__(128) uint32_t g_B1hi[B_B32];
__device__ __align__(128) uint32_t g_B1lo[B_B32];
__device__ unsigned g_bar_count;
__device__ unsigned g_bar_gen;

// ---------------------------------------------------------------------------
__global__ void init_state() {
    int i = blockIdx.x * blockDim.x + threadIdx.x;
    int n = gridDim.x * blockDim.x;
    for (int k = i; k < B_B32; k += n) {
        g_B0hi[k] = 0u; g_B0lo[k] = 0u; g_B1hi[k] = 0u; g_B1lo[k] = 0u;
    }
    for (int k = i; k < NB * NH; k += n) { g_c0[k] = 0.0f; g_c1[k] = 0.0f; }
    if (i == 0) { g_bar_count = 0; g_bar_gen = 0; }
}

// ---------------------------------------------------------------------------
// Split weights -> bf16 hi/lo in mma A-fragment layout.
// region 0: Wh layer0 ; 1: Wh layer1 ; 2: Wx layer1
// Fragment (m16n8k16 row-major A): lane = (row%8)*4 + (kc%8)/2,
//   reg = (kc>=8)*2 + (row%16>=8), half = kc&1
// ---------------------------------------------------------------------------
__global__ __launch_bounds__(256) void prep_weights(const float* __restrict__ Wh,
                                                    const float* __restrict__ Wx) {
    size_t i = (size_t)blockIdx.x * 256 + threadIdx.x;   // 0 .. 3*4M-1
    int r = (int)(i >> 22);
    int rem = (int)(i & 4194303);
    const float* src = (r == 0) ? Wh : (r == 1) ? (Wh + LOFF) : (Wx + LOFF);
    float w = src[rem];
    __nv_bfloat16 hi = __float2bfloat16(w);
    __nv_bfloat16 lo = __float2bfloat16(w - __bfloat162float(hi));
    int j = rem >> 10;           // row in [0,4096)
    int k = rem & 1023;
    int blk = j >> 7;
    int m128 = j & 127;
    int wrp = m128 >> 4;
    int row16 = m128 & 15;
    int k16 = k >> 4;
    int kc = k & 15;
    int lane = (row16 & 7) * 4 + ((kc & 7) >> 1);
    int reg = ((kc >= 8) ? 2 : 0) + ((row16 >= 8) ? 1 : 0);
    int half = kc & 1;
    size_t b32idx = ((((size_t)(r * 32 + blk) * 8 + wrp) * NK16 + k16) * 32 + lane) * 4 + reg;
    size_t bidx = b32idx * 2 + half;
    g_Ahi[bidx] = hi;
    g_Alo[bidx] = lo;
}

// ---------------------------------------------------------------------------
// Precompute xg0[t][j][b] = Wx0 @ x  (fp32 SIMT GEMM)
// ---------------------------------------------------------------------------
__global__ __launch_bounds__(256) void pregemm(const float* __restrict__ Wx,
                                               const float* __restrict__ seq) {
    __shared__ __align__(16) float As[16][132];
    __shared__ __align__(16) float Bs[64][20];

    int tid = threadIdx.x;
    int j0 = blockIdx.y * 128;
    int c0 = blockIdx.x * 64;

    float acc[8][4];
#pragma unroll
    for (int m = 0; m < 8; m++)
#pragma unroll
        for (int n = 0; n < 4; n++) acc[m][n] = 0.0f;

    int m0 = (tid & 15) * 8;
    int n0 = (tid >> 4) * 4;

    int cl = tid >> 2;
    int bkg = tid & 3;
    int c = c0 + cl;
    int bb_ld = c & 31;
    int tt_ld = c >> 5;
    const float* Bcol = seq + ((size_t)bb_ld * NT + tt_ld) * NI + bkg * 4;

    for (int kt = 0; kt < NI / 16; kt++) {
        int k0 = kt * 16;
#pragma unroll
        for (int i = 0; i < 2; i++) {
            int flat = tid + i * 256;
            int row = flat >> 2;
            int akg = flat & 3;
            float4 v = *(const float4*)(Wx + (size_t)(j0 + row) * NI + k0 + akg * 4);
            As[akg * 4 + 0][row] = v.x;
            As[akg * 4 + 1][row] = v.y;
            As[akg * 4 + 2][row] = v.z;
            As[akg * 4 + 3][row] = v.w;
        }
        {
            float4 v = *(const float4*)(Bcol + k0);
            *(float4*)&Bs[cl][bkg * 4] = v;
        }
        __syncthreads();
#pragma unroll
        for (int k = 0; k < 16; k++) {
            float4 a0 = *(float4*)&As[k][m0];
            float4 a1 = *(float4*)&As[k][m0 + 4];
            float av[8] = {a0.x, a0.y, a0.z, a0.w, a1.x, a1.y, a1.z, a1.w};
            float bv[4];
#pragma unroll
            for (int n = 0; n < 4; n++) bv[n] = Bs[n0 + n][k];
#pragma unroll
            for (int m = 0; m < 8; m++) {
                acc[m][0] += av[m] * bv[0];
                acc[m][1] += av[m] * bv[1];
                acc[m][2] += av[m] * bv[2];
                acc[m][3] += av[m] * bv[3];
            }
        }
        __syncthreads();
    }
    int cc = c0 + n0;
    int tt = cc >> 5;
    int bb = cc & 31;
    float* outp = g_xg0 + (size_t)tt * GB + bb;
#pragma unroll
    for (int m = 0; m < 8; m++) {
        int j = j0 + m0 + m;
        *(float4*)(outp + (size_t)j * 32) =
            make_float4(acc[m][0], acc[m][1], acc[m][2], acc[m][3]);
    }
}

// ---------------------------------------------------------------------------
__device__ __forceinline__ float sigf(float x) {
    return 1.0f / (1.0f + __expf(-x));
}
__device__ __forceinline__ float tanhfast(float x) {
    return 2.0f / (1.0f + __expf(-2.0f * x)) - 1.0f;
}

__device__ __forceinline__ void grid_sync(unsigned& gen) {
    __syncthreads();
    if (threadIdx.x == 0) {
        unsigned target = gen + 1;
        __threadfence();
        unsigned arrived = atomicAdd(&g_bar_count, 1u);
        if (arrived == GRID_BLOCKS - 1) {
            atomicExch(&g_bar_count, 0u);
            __threadfence();
            atomicExch(&g_bar_gen, target);
        } else {
            while (*(volatile unsigned*)&g_bar_gen < target) {}
            __threadfence();
        }
        gen = target;
    }
    __syncthreads();
}

// write h (split hi/lo) into B-fragment layout:
//   element (k=hh, n=b): lane = (b&7)*4 + (hh%8)/2, reg = (hh%16)/8, half = hh&1
__device__ __forceinline__ void store_h_split(uint32_t* bhi, uint32_t* blo,
                                              int b, int hh, float hn) {
    int k16 = hh >> 4;
    int kc = hh & 15;
    int n8 = b >> 3;
    int nc = b & 7;
    int lane = nc * 4 + ((kc & 7) >> 1);
    int reg = (kc >= 8) ? 1 : 0;
    int half = kc & 1;
    size_t bidx = (size_t)(((k16 * 4 + n8) * 32 + lane) * 2 + reg) * 2 + half;
    __nv_bfloat16 hi = __float2bfloat16(hn);
    __nv_bfloat16 lo = __float2bfloat16(hn - __bfloat162float(hi));
    ((__nv_bfloat16*)bhi)[bidx] = hi;
    ((__nv_bfloat16*)blo)[bidx] = lo;
}

// ---------------------------------------------------------------------------
// Cell updates:  e<32768 -> layer1 step t ; e>=32768 -> layer0 step t+1
// ---------------------------------------------------------------------------
__device__ void do_update(int t, const float* __restrict__ Bias,
                          float* __restrict__ out) {
    for (int e = blockIdx.x * blockDim.x + threadIdx.x; e < 2 * NB * NH;
         e += GRID_BLOCKS * 256) {
        int e2 = e & 32767;
        int b = e2 & 31;
        int hh = e2 >> 5;
        int gidx = hh * 32 + b;
        if (e < 32768) {                       // layer 1, step t
            if (t < 0) continue;
            float f = g_g1a[gidx]         + g_g1b[gidx]         + Bias[4096 + hh];
            float w = g_g1a[gidx + 32768] + g_g1b[gidx + 32768] + Bias[5120 + hh];
            float i_= g_g1a[gidx + 65536] + g_g1b[gidx + 65536] + Bias[6144 + hh];
            float o = g_g1a[gidx + 98304] + g_g1b[gidx + 98304] + Bias[7168 + hh];
            float cv = g_c1[gidx];
            float cn = cv * sigf(f) + sigf(w) * tanhfast(i_);
            float hn = tanhfast(cn) * sigf(o);
            g_c1[gidx] = cn;
            store_h_split(g_B1hi, g_B1lo, b, hh, hn);
            if (t == NT - 1) out[b * 1024 + hh] = hn;
        } else {                               // layer 0, step t+1
            if (t >= NT - 1) continue;
            const float* gg = g_xg0 + (size_t)(t + 1) * GB;
            float f = gg[gidx]         + Bias[hh];
            float w = gg[gidx + 32768] + Bias[1024 + hh];
            float i_= gg[gidx + 65536] + Bias[2048 + hh];
            float o = gg[gidx + 98304] + Bias[3072 + hh];
            float cv = g_c0[gidx];
            float cn = cv * sigf(f) + sigf(w) * tanhfast(i_);
            float hn = tanhfast(cn) * sigf(o);
            g_c0[gidx] = cn;
            store_h_split(g_B0hi, g_B0lo, b, hh, hn);
        }
    }
}

// ---------------------------------------------------------------------------
__device__ __forceinline__ void mma16816(float* d, const uint4& a,
                                         uint32_t b0, uint32_t b1) {
    asm volatile(
        "mma.sync.aligned.m16n8k16.row.col.f32.bf16.bf16.f32 "
        "{%0,%1,%2,%3},{%4,%5,%6,%7},{%8,%9},{%0,%1,%2,%3};"
        : "+f"(d[0]), "+f"(d[1]), "+f"(d[2]), "+f"(d[3])
        : "r"(a.x), "r"(a.y), "r"(a.z), "r"(a.w), "r"(b0), "r"(b1));
}

// ---------------------------------------------------------------------------
// Persistent LSTM: 96 blocks x 256 threads (8 warps).
//   region0 (bid  0..31): Wh0 @ h0 -> xg0[t+1] +=
//   region1 (bid 32..63): Wh1 @ h1 -> g1a
//   region2 (bid 64..95): Wx1 @ h0 -> g1b
// Per block: M=128 (warp w owns rows w*16..w*16+15), N=32 (4 n8-tiles), K=1024.
// bf16 hi/lo 3-pass via mma.sync m16n8k16, fp32 accum.
// ---------------------------------------------------------------------------
__global__ __launch_bounds__(256, 1) void lstm_persist(
    const float* __restrict__ Bias, float* __restrict__ out) {
    extern __shared__ uint32_t sB[];          // [0:16384) hi, [16384:32768) lo
    uint32_t* sBhi = sB;
    uint32_t* sBlo = sB + B_B32;

    int tid = threadIdx.x;
    int lane = tid & 31;
    int wrp = tid >> 5;
    int bid = blockIdx.x;
    int region = bid >> 5;
    int blk = bid & 31;
    int j0 = blk * 128;

    const uint4* Ahi_w = (const uint4*)g_Ahi +
        (size_t)((region * 32 + blk) * 8 + wrp) * NK16 * 32;
    const uint4* Alo_w = (const uint4*)g_Alo +
        (size_t)((region * 32 + blk) * 8 + wrp) * NK16 * 32;
    const uint4* gBhi = (const uint4*)((region == 1) ? g_B1hi : g_B0hi);
    const uint4* gBlo = (const uint4*)((region == 1) ? g_B1lo : g_B0lo);

    unsigned gen = 0;
    do_update(-1, Bias, out);       // layer0 step 0 (h=c=0)
    grid_sync(gen);

    for (int t = 0; t < NT; t++) {
        if (!(region == 0 && t == NT - 1)) {
            // stage this step's B (hi+lo, 128 KB) into smem
#pragma unroll
            for (int i = 0; i < B_B32 / 4 / 256; i++) {   // 16 iters
                int idx = i * 256 + tid;
                ((uint4*)sBhi)[idx] = gBhi[idx];
                ((uint4*)sBlo)[idx] = gBlo[idx];
            }
            __syncthreads();

            float acc[4][4];
#pragma unroll
            for (int nt = 0; nt < 4; nt++)
#pragma unroll
                for (int q = 0; q < 4; q++) acc[nt][q] = 0.0f;

#pragma unroll 4
            for (int k16 = 0; k16 < NK16; k16++) {
                uint4 ah = Ahi_w[k16 * 32 + lane];
                uint4 al = Alo_w[k16 * 32 + lane];
#pragma unroll
                for (int nt = 0; nt < 4; nt++) {
                    int bix = ((k16 * 4 + nt) * 32 + lane) * 2;
                    uint32_t bh0 = sBhi[bix], bh1 = sBhi[bix + 1];
                    uint32_t bl0 = sBlo[bix], bl1 = sBlo[bix + 1];
                    mma16816(acc[nt], ah, bh0, bh1);
                    mma16816(acc[nt], ah, bl0, bl1);
                    mma16816(acc[nt], al, bh0, bh1);
                }
            }
            __syncthreads();

            // epilogue: D rows r=(w*16 + lane/4) and r+8; cols c=nt*8+(lane%4)*2
            int r0 = j0 + wrp * 16 + (lane >> 2);
            int cc = (lane & 3) * 2;
            if (region == 0) {
                float* g0 = g_xg0 + (size_t)(t + 1) * GB;
#pragma unroll
                for (int nt = 0; nt < 4; nt++) {
                    float2* p0 = (float2*)(g0 + (size_t)r0 * 32 + nt * 8 + cc);
                    float2* p1 = (float2*)(g0 + (size_t)(r0 + 8) * 32 + nt * 8 + cc);
                    float2 v0 = *p0, v1 = *p1;
                    v0.x += acc[nt][0]; v0.y += acc[nt][1];
                    v1.x += acc[nt][2]; v1.y += acc[nt][3];
                    *p0 = v0; *p1 = v1;
                }
            } else {
                float* g0 = (region == 1) ? g_g1a : g_g1b;
#pragma unroll
                for (int nt = 0; nt < 4; nt++) {
                    *(float2*)(g0 + (size_t)r0 * 32 + nt * 8 + cc) =
                        make_float2(acc[nt][0], acc[nt][1]);
                    *(float2*)(g0 + (size_t)(r0 + 8) * 32 + nt * 8 + cc) =
                        make_float2(acc[nt][2], acc[nt][3]);
                }
            }
        }
        grid_sync(gen);
        do_update(t, Bias, out);
        if (t < NT - 1) grid_sync(gen);
    }
}

// ---------------------------------------------------------------------------
extern "C" void kernel_launch(void* const* d_in, const int* in_sizes, int n_in,
                              void* d_out, int out_size) {
    const float* seq  = (const float*)d_in[0];  // (32, 512, 1024)
    const float* Wh   = (const float*)d_in[1];  // (2, 4, 1024, 1024)
    const float* Wx   = (const float*)d_in[2];  // (2, 4, 1024, 1024)
    const float* Bias = (const float*)d_in[3];  // (2, 4, 1024)
    float* out = (float*)d_out;                 // (32, 1024)

    cudaFuncSetAttribute(lstm_persist,
                         cudaFuncAttributeMaxDynamicSharedMemorySize, SMEM_BYTES);

    init_state<<<64, 256>>>();
    prep_weights<<<3 * 4096 * 1024 / 256, 256>>>(Wh, Wx);
    pregemm<<<dim3(NT * NB / 64, NG / 128), 256>>>(Wx, seq);
    lstm_persist<<<GRID_BLOCKS, 256, SMEM_BYTES>>>(Bias, out);
}

// round 5
// speedup vs baseline: 4.1175x; 1.5721x over previous
#include <cuda_runtime.h>
#include <cuda_fp16.h>
#include <math.h>
#include <stdint.h>

#define NB 32
#define NT 512
#define NI 1024
#define NH 1024
#define NG 4096
#define GB (NG*NB)              // gate elems per step, layout [j][b]
#define LOFF (4*NH*NI)
#define GRID_BLOCKS 96
#define NK16 64                 // K=1024 in 64 chunks of 16
#define B_B32 16384             // one B operand (hi or lo) in b32: 64*4*32*2
#define SMEM_BYTES (2 * B_B32 * 4)   // 128 KB: Bhi + Blo (persistent)
#define PRE_SMEM 65536               // 64 KB: sBh + sBl (pregemm)

// ---------------- device scratch -------------------------------------------
__device__ __align__(256) float g_xg0[(size_t)(NT + 1) * GB]; // [t][j][b]
__device__ __align__(256) float g_g1a[GB];
__device__ __align__(256) float g_g1b[GB];
__device__ float g_c0[NB * NH];
__device__ float g_c1[NB * NH];
// A operands (fp16 hi/lo) in m16n8k16 A-fragment layout:
//   [mat(4)][blk(32)][warp(8)][k16(64)][lane(32)][reg(4) b32] ; mat3 = Wx layer0
__device__ __align__(128) __half g_Ahi[(size_t)4 * 4096 * 1024];
__device__ __align__(128) __half g_Alo[(size_t)4 * 4096 * 1024];
// seq in B-fragment layout (fp16 hi/lo): [k16(64)][n8(2048)][lane(32)][reg(2)][half(2)]
__device__ __align__(128) __half g_Sh[(size_t)64 * 2048 * 128];
__device__ __align__(128) __half g_Sl[(size_t)64 * 2048 * 128];
// h vectors in B-fragment layout (fp16 hi/lo): [k16(64)][n8(4)][lane(32)][reg(2)] b32
__device__ __align__(128) uint32_t g_B0hi[B_B32];
__device__ __align__(128) uint32_t g_B0lo[B_B32];
__device__ __align__(128) uint32_t g_B1hi[B_B32];
__device__ __align__(128) uint32_t g_B1lo[B_B32];
__device__ unsigned g_bar_count;
__device__ unsigned g_bar_gen;

// ---------------------------------------------------------------------------
__global__ void init_state() {
    int i = blockIdx.x * blockDim.x + threadIdx.x;
    int n = gridDim.x * blockDim.x;
    for (int k = i; k < B_B32; k += n) {
        g_B0hi[k] = 0u; g_B0lo[k] = 0u; g_B1hi[k] = 0u; g_B1lo[k] = 0u;
    }
    for (int k = i; k < NB * NH; k += n) { g_c0[k] = 0.0f; g_c1[k] = 0.0f; }
    if (i == 0) { g_bar_count = 0; g_bar_gen = 0; }
}

// ---------------------------------------------------------------------------
// Split weights -> fp16 hi/lo in mma A-fragment layout.
// mat 0: Wh layer0 ; 1: Wh layer1 ; 2: Wx layer1 ; 3: Wx layer0 (pregemm)
// ---------------------------------------------------------------------------
__global__ __launch_bounds__(256) void prep_weights(const float* __restrict__ Wh,
                                                    const float* __restrict__ Wx) {
    size_t i = (size_t)blockIdx.x * 256 + threadIdx.x;   // 0 .. 4*4M-1
    int r = (int)(i >> 22);
    int rem = (int)(i & 4194303);
    const float* src = (r == 0) ? Wh : (r == 1) ? (Wh + LOFF)
                     : (r == 2) ? (Wx + LOFF) : Wx;
    float w = src[rem];
    __half hi = __float2half_rn(w);
    __half lo = __float2half_rn(w - __half2float(hi));
    int j = rem >> 10;
    int k = rem & 1023;
    int blk = j >> 7;
    int m128 = j & 127;
    int wrp = m128 >> 4;
    int row16 = m128 & 15;
    int k16 = k >> 4;
    int kc = k & 15;
    int lane = (row16 & 7) * 4 + ((kc & 7) >> 1);
    int reg = ((kc >= 8) ? 2 : 0) + ((row16 >= 8) ? 1 : 0);
    int half = kc & 1;
    size_t b32idx = ((((size_t)(r * 32 + blk) * 8 + wrp) * NK16 + k16) * 32 + lane) * 4 + reg;
    size_t bidx = b32idx * 2 + half;
    g_Ahi[bidx] = hi;
    g_Alo[bidx] = lo;
}

// ---------------------------------------------------------------------------
// seq -> fp16 hi/lo B-fragment layout. column c = t*32+b, k = input dim.
// ---------------------------------------------------------------------------
__global__ __launch_bounds__(256) void prep_seq(const float* __restrict__ seq) {
    size_t i = (size_t)blockIdx.x * 256 + threadIdx.x;   // 0 .. 16.8M-1
    float v = seq[i];
    __half hi = __float2half_rn(v);
    __half lo = __float2half_rn(v - __half2float(hi));
    int b = (int)(i >> 19);
    int t = (int)(i >> 10) & 511;
    int k = (int)i & 1023;
    int c = t * 32 + b;
    int k16 = k >> 4, kc = k & 15;
    int n8 = c >> 3, nc = c & 7;
    int lane = nc * 4 + ((kc & 7) >> 1);
    int reg = (kc >= 8) ? 1 : 0;
    int half = kc & 1;
    size_t idx = ((((size_t)k16 * 2048 + n8) * 32 + lane) * 2 + reg) * 2 + half;
    g_Sh[idx] = hi;
    g_Sl[idx] = lo;
}

// ---------------------------------------------------------------------------
__device__ __forceinline__ void mma_f16(float* d, const uint4& a,
                                        uint32_t b0, uint32_t b1) {
    asm volatile(
        "mma.sync.aligned.m16n8k16.row.col.f32.f16.f16.f32 "
        "{%0,%1,%2,%3},{%4,%5,%6,%7},{%8,%9},{%0,%1,%2,%3};"
        : "+f"(d[0]), "+f"(d[1]), "+f"(d[2]), "+f"(d[3])
        : "r"(a.x), "r"(a.y), "r"(a.z), "r"(a.w), "r"(b0), "r"(b1));
}

// ---------------------------------------------------------------------------
// Pregemm on tensor cores: xg0[t][j][b] = Wx0 @ x, fp16 hi/lo 3-pass.
// Grid (32 Mblk, 128 Nblk), 256 thr. Tile M=128 x N=128, K=1024 in 8 chunks.
// ---------------------------------------------------------------------------
__global__ __launch_bounds__(256) void pregemm_mma() {
    extern __shared__ uint32_t sm[];          // sBh[8192] + sBl[8192] b32
    uint32_t* sBh = sm;
    uint32_t* sBl = sm + 8192;

    int tid = threadIdx.x;
    int lane = tid & 31;
    int wrp = tid >> 5;
    int blkM = blockIdx.x;    // 0..31
    int blkN = blockIdx.y;    // 0..127

    const uint4* Ah_w = (const uint4*)g_Ahi + (size_t)((96 + blkM) * 8 + wrp) * NK16 * 32;
    const uint4* Al_w = (const uint4*)g_Alo + (size_t)((96 + blkM) * 8 + wrp) * NK16 * 32;
    const uint4* gSh = (const uint4*)g_Sh;
    const uint4* gSl = (const uint4*)g_Sl;

    float acc[16][4];
#pragma unroll
    for (int nn = 0; nn < 16; nn++)
#pragma unroll
        for (int q = 0; q < 4; q++) acc[nn][q] = 0.0f;

    for (int kc8 = 0; kc8 < 8; kc8++) {
        // stage B chunk: 8 k16 x 16 n8, hi+lo (2048 uint4 each)
#pragma unroll
        for (int it = 0; it < 8; it++) {
            int flat = it * 256 + tid;
            int kk = flat >> 8;
            int rem = flat & 255;
            int nn = rem >> 4;
            int q = rem & 15;
            size_t srcu4 = ((size_t)(kc8 * 8 + kk) * 2048 + blkN * 16 + nn) * 16 + q;
            ((uint4*)sBh)[flat] = gSh[srcu4];
            ((uint4*)sBl)[flat] = gSl[srcu4];
        }
        __syncthreads();
#pragma unroll 2
        for (int kk = 0; kk < 8; kk++) {
            int k16 = kc8 * 8 + kk;
            uint4 ah = Ah_w[k16 * 32 + lane];
            uint4 al = Al_w[k16 * 32 + lane];
#pragma unroll
            for (int nn = 0; nn < 16; nn++) {
                int bix = ((kk * 16 + nn) * 32 + lane) * 2;
                uint32_t bh0 = sBh[bix], bh1 = sBh[bix + 1];
                uint32_t bl0 = sBl[bix], bl1 = sBl[bix + 1];
                mma_f16(acc[nn], ah, bh0, bh1);
                mma_f16(acc[nn], ah, bl0, bl1);
                mma_f16(acc[nn], al, bh0, bh1);
            }
        }
        __syncthreads();
    }
    // epilogue: rows r0, r0+8 ; cols c = blkN*128 + nn*8 + (lane%4)*2
    int r0 = blkM * 128 + wrp * 16 + (lane >> 2);
    int ccl = (lane & 3) * 2;
#pragma unroll
    for (int nn = 0; nn < 16; nn++) {
        int c = blkN * 128 + nn * 8 + ccl;
        int t = c >> 5;
        int b = c & 31;
        float* base = g_xg0 + (size_t)t * GB + b;
        *(float2*)(base + (size_t)r0 * 32) = make_float2(acc[nn][0], acc[nn][1]);
        *(float2*)(base + (size_t)(r0 + 8) * 32) = make_float2(acc[nn][2], acc[nn][3]);
    }
}

// ---------------------------------------------------------------------------
__device__ __forceinline__ float sigf(float x) {
    return 1.0f / (1.0f + __expf(-x));
}
__device__ __forceinline__ float tanhfast(float x) {
    return 2.0f / (1.0f + __expf(-2.0f * x)) - 1.0f;
}

__device__ __forceinline__ void grid_sync(unsigned& gen) {
    __syncthreads();
    if (threadIdx.x == 0) {
        unsigned target = gen + 1;
        __threadfence();
        unsigned arrived = atomicAdd(&g_bar_count, 1u);
        if (arrived == GRID_BLOCKS - 1) {
            atomicExch(&g_bar_count, 0u);
            __threadfence();
            atomicExch(&g_bar_gen, target);
        } else {
            while (*(volatile unsigned*)&g_bar_gen < target) {}
            __threadfence();
        }
        gen = target;
    }
    __syncthreads();
}

// write h (fp16 hi/lo) into B-fragment layout
__device__ __forceinline__ void store_h_split(uint32_t* bhi, uint32_t* blo,
                                              int b, int hh, float hn) {
    int k16 = hh >> 4;
    int kc = hh & 15;
    int n8 = b >> 3;
    int nc = b & 7;
    int lane = nc * 4 + ((kc & 7) >> 1);
    int reg = (kc >= 8) ? 1 : 0;
    int half = kc & 1;
    size_t bidx = (size_t)(((k16 * 4 + n8) * 32 + lane) * 2 + reg) * 2 + half;
    __half hi = __float2half_rn(hn);
    __half lo = __float2half_rn(hn - __half2float(hi));
    ((__half*)bhi)[bidx] = hi;
    ((__half*)blo)[bidx] = lo;
}

// ---------------------------------------------------------------------------
// Cell updates:  e<32768 -> layer1 step t ; e>=32768 -> layer0 step t+1
// ---------------------------------------------------------------------------
__device__ void do_update(int t, const float* __restrict__ Bias,
                          float* __restrict__ out) {
    for (int e = blockIdx.x * blockDim.x + threadIdx.x; e < 2 * NB * NH;
         e += GRID_BLOCKS * 256) {
        int e2 = e & 32767;
        int b = e2 & 31;
        int hh = e2 >> 5;
        int gidx = hh * 32 + b;
        if (e < 32768) {                       // layer 1, step t
            if (t < 0) continue;
            float f = g_g1a[gidx]         + g_g1b[gidx]         + Bias[4096 + hh];
            float w = g_g1a[gidx + 32768] + g_g1b[gidx + 32768] + Bias[5120 + hh];
            float i_= g_g1a[gidx + 65536] + g_g1b[gidx + 65536] + Bias[6144 + hh];
            float o = g_g1a[gidx + 98304] + g_g1b[gidx + 98304] + Bias[7168 + hh];
            float cv = g_c1[gidx];
            float cn = cv * sigf(f) + sigf(w) * tanhfast(i_);
            float hn = tanhfast(cn) * sigf(o);
            g_c1[gidx] = cn;
            store_h_split(g_B1hi, g_B1lo, b, hh, hn);
            if (t == NT - 1) out[b * 1024 + hh] = hn;
        } else {                               // layer 0, step t+1
            if (t >= NT - 1) continue;
            const float* gg = g_xg0 + (size_t)(t + 1) * GB;
            float f = gg[gidx]         + Bias[hh];
            float w = gg[gidx + 32768] + Bias[1024 + hh];
            float i_= gg[gidx + 65536] + Bias[2048 + hh];
            float o = gg[gidx + 98304] + Bias[3072 + hh];
            float cv = g_c0[gidx];
            float cn = cv * sigf(f) + sigf(w) * tanhfast(i_);
            float hn = tanhfast(cn) * sigf(o);
            g_c0[gidx] = cn;
            store_h_split(g_B0hi, g_B0lo, b, hh, hn);
        }
    }
}

// ---------------------------------------------------------------------------
// Persistent LSTM: 96 blocks x 256 threads (8 warps).
//   region0 (bid  0..31): Wh0 @ h0 -> xg0[t+1] +=
//   region1 (bid 32..63): Wh1 @ h1 -> g1a
//   region2 (bid 64..95): Wx1 @ h0 -> g1b
// A single fp16, B = h split fp16 hi/lo: 2-pass mma (Ah*Bh + Ah*Bl).
// ---------------------------------------------------------------------------
__global__ __launch_bounds__(256, 1) void lstm_persist(
    const float* __restrict__ Bias, float* __restrict__ out) {
    extern __shared__ uint32_t sB[];          // [0:16384) hi, [16384:32768) lo
    uint32_t* sBhi = sB;
    uint32_t* sBlo = sB + B_B32;

    int tid = threadIdx.x;
    int lane = tid & 31;
    int wrp = tid >> 5;
    int bid = blockIdx.x;
    int region = bid >> 5;
    int blk = bid & 31;
    int j0 = blk * 128;

    const uint4* Ah_w = (const uint4*)g_Ahi +
        (size_t)((region * 32 + blk) * 8 + wrp) * NK16 * 32;
    const uint4* gBhi = (const uint4*)((region == 1) ? g_B1hi : g_B0hi);
    const uint4* gBlo = (const uint4*)((region == 1) ? g_B1lo : g_B0lo);

    unsigned gen = 0;
    do_update(-1, Bias, out);       // layer0 step 0 (h=c=0)
    grid_sync(gen);

    for (int t = 0; t < NT; t++) {
        if (!(region == 0 && t == NT - 1)) {
            // stage this step's B (hi+lo, 128 KB) into smem
#pragma unroll
            for (int i = 0; i < B_B32 / 4 / 256; i++) {   // 16 iters
                int idx = i * 256 + tid;
                ((uint4*)sBhi)[idx] = gBhi[idx];
                ((uint4*)sBlo)[idx] = gBlo[idx];
            }
            __syncthreads();

            float acc[4][4];
#pragma unroll
            for (int nt = 0; nt < 4; nt++)
#pragma unroll
                for (int q = 0; q < 4; q++) acc[nt][q] = 0.0f;

#pragma unroll 8
            for (int k16 = 0; k16 < NK16; k16++) {
                uint4 ah = Ah_w[k16 * 32 + lane];
#pragma unroll
                for (int nt = 0; nt < 4; nt++) {
                    int bix = ((k16 * 4 + nt) * 32 + lane) * 2;
                    uint32_t bh0 = sBhi[bix], bh1 = sBhi[bix + 1];
                    uint32_t bl0 = sBlo[bix], bl1 = sBlo[bix + 1];
                    mma_f16(acc[nt], ah, bh0, bh1);
                    mma_f16(acc[nt], ah, bl0, bl1);
                }
            }
            __syncthreads();

            // epilogue: D rows r0, r0+8 ; cols c = nt*8 + (lane%4)*2
            int r0 = j0 + wrp * 16 + (lane >> 2);
            int cc = (lane & 3) * 2;
            if (region == 0) {
                float* g0 = g_xg0 + (size_t)(t + 1) * GB;
#pragma unroll
                for (int nt = 0; nt < 4; nt++) {
                    float2* p0 = (float2*)(g0 + (size_t)r0 * 32 + nt * 8 + cc);
                    float2* p1 = (float2*)(g0 + (size_t)(r0 + 8) * 32 + nt * 8 + cc);
                    float2 v0 = *p0, v1 = *p1;
                    v0.x += acc[nt][0]; v0.y += acc[nt][1];
                    v1.x += acc[nt][2]; v1.y += acc[nt][3];
                    *p0 = v0; *p1 = v1;
                }
            } else {
                float* g0 = (region == 1) ? g_g1a : g_g1b;
#pragma unroll
                for (int nt = 0; nt < 4; nt++) {
                    *(float2*)(g0 + (size_t)r0 * 32 + nt * 8 + cc) =
                        make_float2(acc[nt][0], acc[nt][1]);
                    *(float2*)(g0 + (size_t)(r0 + 8) * 32 + nt * 8 + cc) =
                        make_float2(acc[nt][2], acc[nt][3]);
                }
            }
        }
        grid_sync(gen);
        do_update(t, Bias, out);
        if (t < NT - 1) grid_sync(gen);
    }
}

// ---------------------------------------------------------------------------
extern "C" void kernel_launch(void* const* d_in, const int* in_sizes, int n_in,
                              void* d_out, int out_size) {
    const float* seq  = (const float*)d_in[0];  // (32, 512, 1024)
    const float* Wh   = (const float*)d_in[1];  // (2, 4, 1024, 1024)
    const float* Wx   = (const float*)d_in[2];  // (2, 4, 1024, 1024)
    const float* Bias = (const float*)d_in[3];  // (2, 4, 1024)
    float* out = (float*)d_out;                 // (32, 1024)

    cudaFuncSetAttribute(lstm_persist,
                         cudaFuncAttributeMaxDynamicSharedMemorySize, SMEM_BYTES);
    cudaFuncSetAttribute(pregemm_mma,
                         cudaFuncAttributeMaxDynamicSharedMemorySize, PRE_SMEM);

    init_state<<<64, 256>>>();
    prep_weights<<<4 * 4096 * 1024 / 256, 256>>>(Wh, Wx);
    prep_seq<<<NB * NT * NI / 256, 256>>>(seq);
    pregemm_mma<<<dim3(32, 128), 256, PRE_SMEM>>>();
    lstm_persist<<<GRID_BLOCKS, 256, SMEM_BYTES>>>(Bias, out);
}

// round 6
// speedup vs baseline: 4.8518x; 1.1784x over previous
#include <cuda_runtime.h>
#include <cuda_fp16.h>
#include <math.h>
#include <stdint.h>

#define NB 32
#define NT 512
#define NI 1024
#define NH 1024
#define NG 4096
#define GB (NG*NB)              // gate elems per step, layout [t][j'][b]
#define LOFF (4*NH*NI)
#define GRID_BLOCKS 96
#define NK16 64                 // K=1024 in 64 chunks of 16
#define B_B32 16384             // one B operand (hi or lo) in b32: 64*4*32*2
#define MAT_U4 524288           // uint4 stride per A matrix (4096x1024 fp16)
#define SMEM_BYTES (131072 + 16384 + 4096)   // sB(128K) + sTile(16K) + sC(4K)
#define PRE_SMEM 65536

// ---------------- device scratch -------------------------------------------
__device__ __align__(256) float g_xg0[(size_t)(NT + 1) * GB]; // [t][j'][b]
// A fragments fp16 (hi; lo used by pregemm only), m16n8k16 A layout.
// mat0 Wh0 (interleaved rows, 32 blks x 8 warps), mat1 Wh1 / mat2 Wx1
// (interleaved rows, 64 blks x 4 tiles), mat3 Wx0 (original rows).
__device__ __align__(128) __half g_Ahi[(size_t)4 * 4096 * 1024];
__device__ __align__(128) __half g_Alo[(size_t)4 * 4096 * 1024];
// seq B-fragments (hi/lo)
__device__ __align__(128) __half g_Sh[(size_t)64 * 2048 * 128];
__device__ __align__(128) __half g_Sl[(size_t)64 * 2048 * 128];
// h B-fragments, double-buffered by step parity
__device__ __align__(128) uint32_t g_B0hi[2][B_B32];
__device__ __align__(128) uint32_t g_B0lo[2][B_B32];
__device__ __align__(128) uint32_t g_B1hi[2][B_B32];
__device__ __align__(128) uint32_t g_B1lo[2][B_B32];
__device__ unsigned g_bar_count;
__device__ unsigned g_bar_gen;

// ---------------------------------------------------------------------------
__global__ void init_state() {
    int i = blockIdx.x * blockDim.x + threadIdx.x;
    int n = gridDim.x * blockDim.x;
    for (int k = i; k < B_B32; k += n) {
        g_B0hi[0][k] = 0u; g_B0lo[0][k] = 0u;
        g_B0hi[1][k] = 0u; g_B0lo[1][k] = 0u;
        g_B1hi[0][k] = 0u; g_B1lo[0][k] = 0u;
        g_B1hi[1][k] = 0u; g_B1lo[1][k] = 0u;
    }
    if (i == 0) { g_bar_count = 0; g_bar_gen = 0; }
}

// ---------------------------------------------------------------------------
// Weights -> fp16 hi/lo A-fragments.  mats 0-2 use interleaved rows j'=hh*4+g.
// ---------------------------------------------------------------------------
__global__ __launch_bounds__(256) void prep_weights(const float* __restrict__ Wh,
                                                    const float* __restrict__ Wx) {
    size_t i = (size_t)blockIdx.x * 256 + threadIdx.x;   // 0 .. 4*4M-1
    int r = (int)(i >> 22);
    int rem = (int)(i & 4194303);
    const float* src = (r == 0) ? Wh : (r == 1) ? (Wh + LOFF)
                     : (r == 2) ? (Wx + LOFF) : Wx;
    float w = src[rem];
    __half hi = __float2half_rn(w);
    __half lo = __float2half_rn(w - __half2float(hi));
    int j = rem >> 10;           // original row g*1024+hh
    int k = rem & 1023;
    int k16 = k >> 4;
    int kc = k & 15;
    size_t frag;                 // uint4 index within mat
    if (r == 3) {
        int blk = j >> 7, wrp = (j >> 4) & 7, row16 = j & 15;
        int lane = (row16 & 7) * 4 + ((kc & 7) >> 1);
        frag = ((size_t)(blk * 8 + wrp) * 64 + k16) * 32 + lane;
        int reg = ((kc >= 8) ? 2 : 0) + ((row16 >= 8) ? 1 : 0);
        size_t bidx = (frag * 4 + reg) * 2 + (kc & 1) + (size_t)r * 4194304;
        g_Ahi[bidx] = hi; g_Alo[bidx] = lo;
        return;
    }
    int g = j >> 10, hh = j & 1023;
    int jp = hh * 4 + g;
    int row16 = jp & 15;
    int lane = (row16 & 7) * 4 + ((kc & 7) >> 1);
    int reg = ((kc >= 8) ? 2 : 0) + ((row16 >= 8) ? 1 : 0);
    if (r == 0) {
        int blk = jp >> 7, wrp = (jp >> 4) & 7;
        frag = ((size_t)(blk * 8 + wrp) * 64 + k16) * 32 + lane;
    } else {
        int blk = jp >> 6, tile = (jp >> 4) & 3;
        frag = ((size_t)(blk * 4 + tile) * 64 + k16) * 32 + lane;
    }
    size_t bidx = (frag * 4 + reg) * 2 + (kc & 1) + (size_t)r * 4194304;
    g_Ahi[bidx] = hi; g_Alo[bidx] = lo;
}

// ---------------------------------------------------------------------------
__global__ __launch_bounds__(256) void prep_seq(const float* __restrict__ seq) {
    size_t i = (size_t)blockIdx.x * 256 + threadIdx.x;
    float v = seq[i];
    __half hi = __float2half_rn(v);
    __half lo = __float2half_rn(v - __half2float(hi));
    int b = (int)(i >> 19);
    int t = (int)(i >> 10) & 511;
    int k = (int)i & 1023;
    int c = t * 32 + b;
    int k16 = k >> 4, kc = k & 15;
    int n8 = c >> 3, nc = c & 7;
    int lane = nc * 4 + ((kc & 7) >> 1);
    int reg = (kc >= 8) ? 1 : 0;
    size_t idx = ((((size_t)k16 * 2048 + n8) * 32 + lane) * 2 + reg) * 2 + (kc & 1);
    g_Sh[idx] = hi;
    g_Sl[idx] = lo;
}

// ---------------------------------------------------------------------------
__device__ __forceinline__ void mma_f16(float* d, const uint4& a,
                                        uint32_t b0, uint32_t b1) {
    asm volatile(
        "mma.sync.aligned.m16n8k16.row.col.f32.f16.f16.f32 "
        "{%0,%1,%2,%3},{%4,%5,%6,%7},{%8,%9},{%0,%1,%2,%3};"
        : "+f"(d[0]), "+f"(d[1]), "+f"(d[2]), "+f"(d[3])
        : "r"(a.x), "r"(a.y), "r"(a.z), "r"(a.w), "r"(b0), "r"(b1));
}

// ---------------------------------------------------------------------------
// Pregemm: xg0[t][j'][b] = Wx0 @ x, fp16 hi/lo 3-pass. Epilogue remaps rows
// to the interleaved order j' = hh*4 + g.
// ---------------------------------------------------------------------------
__global__ __launch_bounds__(256) void pregemm_mma() {
    extern __shared__ uint32_t sm[];
    uint32_t* sBh = sm;
    uint32_t* sBl = sm + 8192;

    int tid = threadIdx.x;
    int lane = tid & 31;
    int wrp = tid >> 5;
    int blkM = blockIdx.x;
    int blkN = blockIdx.y;

    const uint4* Ah_w = (const uint4*)g_Ahi + 3 * MAT_U4 +
        (size_t)(blkM * 8 + wrp) * NK16 * 32;
    const uint4* Al_w = (const uint4*)g_Alo + 3 * MAT_U4 +
        (size_t)(blkM * 8 + wrp) * NK16 * 32;
    const uint4* gSh = (const uint4*)g_Sh;
    const uint4* gSl = (const uint4*)g_Sl;

    float acc[16][4];
#pragma unroll
    for (int nn = 0; nn < 16; nn++)
#pragma unroll
        for (int q = 0; q < 4; q++) acc[nn][q] = 0.0f;

    for (int kc8 = 0; kc8 < 8; kc8++) {
#pragma unroll
        for (int it = 0; it < 8; it++) {
            int flat = it * 256 + tid;
            int kk = flat >> 8;
            int rem = flat & 255;
            int nn = rem >> 4;
            int q = rem & 15;
            size_t srcu4 = ((size_t)(kc8 * 8 + kk) * 2048 + blkN * 16 + nn) * 16 + q;
            ((uint4*)sBh)[flat] = gSh[srcu4];
            ((uint4*)sBl)[flat] = gSl[srcu4];
        }
        __syncthreads();
#pragma unroll 2
        for (int kk = 0; kk < 8; kk++) {
            int k16 = kc8 * 8 + kk;
            uint4 ah = Ah_w[k16 * 32 + lane];
            uint4 al = Al_w[k16 * 32 + lane];
#pragma unroll
            for (int nn = 0; nn < 16; nn++) {
                int bix = ((kk * 16 + nn) * 32 + lane) * 2;
                uint32_t bh0 = sBh[bix], bh1 = sBh[bix + 1];
                uint32_t bl0 = sBl[bix], bl1 = sBl[bix + 1];
                mma_f16(acc[nn], ah, bh0, bh1);
                mma_f16(acc[nn], ah, bl0, bl1);
                mma_f16(acc[nn], al, bh0, bh1);
            }
        }
        __syncthreads();
    }
    int j0a = blkM * 128 + wrp * 16 + (lane >> 2);
    int j0b = j0a + 8;
    int ja = (j0a & 1023) * 4 + (j0a >> 10);
    int jb = (j0b & 1023) * 4 + (j0b >> 10);
    int ccl = (lane & 3) * 2;
#pragma unroll
    for (int nn = 0; nn < 16; nn++) {
        int c = blkN * 128 + nn * 8 + ccl;
        int t = c >> 5;
        int b = c & 31;
        float* base = g_xg0 + (size_t)t * GB + b;
        *(float2*)(base + (size_t)ja * 32) = make_float2(acc[nn][0], acc[nn][1]);
        *(float2*)(base + (size_t)jb * 32) = make_float2(acc[nn][2], acc[nn][3]);
    }
}

// ---------------------------------------------------------------------------
__device__ __forceinline__ float sigf(float x) {
    return 1.0f / (1.0f + __expf(-x));
}
__device__ __forceinline__ float tanhfast(float x) {
    return 2.0f / (1.0f + __expf(-2.0f * x)) - 1.0f;
}

__device__ __forceinline__ void grid_sync(unsigned& gen) {
    __syncthreads();
    if (threadIdx.x == 0) {
        unsigned target = gen + 1;
        __threadfence();
        unsigned arrived = atomicAdd(&g_bar_count, 1u);
        if (arrived == GRID_BLOCKS - 1) {
            atomicExch(&g_bar_count, 0u);
            __threadfence();
            atomicExch(&g_bar_gen, target);
        } else {
            while (*(volatile unsigned*)&g_bar_gen < target) {}
            __threadfence();
        }
        gen = target;
    }
    __syncthreads();
}

// write h (fp16 hi/lo) into B-fragment layout
__device__ __forceinline__ void store_h_split(uint32_t* bhi, uint32_t* blo,
                                              int b, int hh, float hn) {
    int k16 = hh >> 4;
    int kc = hh & 15;
    int n8 = b >> 3;
    int nc = b & 7;
    int lane = nc * 4 + ((kc & 7) >> 1);
    int reg = (kc >= 8) ? 1 : 0;
    size_t bidx = (size_t)(((k16 * 4 + n8) * 32 + lane) * 2 + reg) * 2 + (kc & 1);
    __half hi = __float2half_rn(hn);
    __half lo = __float2half_rn(hn - __half2float(hi));
    ((__half*)bhi)[bidx] = hi;
    ((__half*)blo)[bidx] = lo;
}

// ---------------------------------------------------------------------------
// Persistent LSTM: 96 blocks x 256 threads, ONE grid barrier per step.
//   L0 (bid 0..31):  M=128 interleaved gate rows (32 hh), K=1024 Wh0@h0.
//   L1 (bid 32..95): M=64 (16 hh), K=2048 = Wh1@h1 then Wx1@h0 (two phases).
// Each block runs the cell update for its own hh rows in the epilogue;
// c state lives in SMEM for the whole kernel.
// ---------------------------------------------------------------------------
__global__ __launch_bounds__(256, 1) void lstm_persist(
    const float* __restrict__ Bias, float* __restrict__ out) {
    extern __shared__ uint32_t sm[];
    uint32_t* sBhi = sm;                         // 64 KB
    uint32_t* sBlo = sm + B_B32;                 // 64 KB
    float* sTile = (float*)(sm + 2 * B_B32);     // 16 KB
    float* sC = sTile + 4096;                    // 4 KB

    int tid = threadIdx.x;
    int lane = tid & 31;
    int wrp = tid >> 5;
    int bid = blockIdx.x;
    int region = (bid < 32) ? 0 : 1;

    unsigned gen = 0;

    if (region == 0) {
        // ------------------------------ LAYER 0 ------------------------------
        int blk = bid;
        const uint4* Ah_w = (const uint4*)g_Ahi +
            (size_t)(blk * 8 + wrp) * NK16 * 32;

        float bf[4], bw[4], bi_[4], bo[4];
#pragma unroll
        for (int i = 0; i < 4; i++) {
            int hh = blk * 32 + ((tid + i * 256) >> 5);
            bf[i] = Bias[hh]; bw[i] = Bias[1024 + hh];
            bi_[i] = Bias[2048 + hh]; bo[i] = Bias[3072 + hh];
        }

        // prologue: h0(0) = cell(c=0, xg0[0] + bias)
        {
            const float* xg = g_xg0 + (size_t)blk * 128 * 32;
#pragma unroll
            for (int i = 0; i < 4; i++) {
                int q = tid + i * 256;
                int hh_l = q >> 5, b = q & 31, br = hh_l * 4;
                float w = xg[(br + 1) * 32 + b] + bw[i];
                float i_ = xg[(br + 2) * 32 + b] + bi_[i];
                float o = xg[(br + 3) * 32 + b] + bo[i];
                float cn = sigf(w) * tanhfast(i_);
                float hn = tanhfast(cn) * sigf(o);
                sC[q] = cn;
                store_h_split(g_B0hi[0], g_B0lo[0], b, blk * 32 + hh_l, hn);
            }
        }

        for (int n = 0; n < NT; n++) {
            grid_sync(gen);
            if (n >= NT - 1) continue;          // no h0(512)
            int p = n & 1;
            // stage h0(n) fragments
            {
                const uint4* srcH = (const uint4*)g_B0hi[p];
                const uint4* srcL = (const uint4*)g_B0lo[p];
#pragma unroll
                for (int i = 0; i < 16; i++) {
                    int idx = i * 256 + tid;
                    ((uint4*)sBhi)[idx] = srcH[idx];
                    ((uint4*)sBlo)[idx] = srcL[idx];
                }
            }
            __syncthreads();

            float acc[4][4];
#pragma unroll
            for (int nt = 0; nt < 4; nt++)
#pragma unroll
                for (int q = 0; q < 4; q++) acc[nt][q] = 0.0f;
#pragma unroll 8
            for (int k16 = 0; k16 < NK16; k16++) {
                uint4 ah = Ah_w[k16 * 32 + lane];
#pragma unroll
                for (int nt = 0; nt < 4; nt++) {
                    int bix = ((k16 * 4 + nt) * 32 + lane) * 2;
                    mma_f16(acc[nt], ah, sBhi[bix], sBhi[bix + 1]);
                    mma_f16(acc[nt], ah, sBlo[bix], sBlo[bix + 1]);
                }
            }
            // epilogue -> smem tile
            int r0 = wrp * 16 + (lane >> 2);
            int cc = (lane & 3) * 2;
#pragma unroll
            for (int nt = 0; nt < 4; nt++) {
                *(float2*)&sTile[r0 * 32 + nt * 8 + cc] =
                    make_float2(acc[nt][0], acc[nt][1]);
                *(float2*)&sTile[(r0 + 8) * 32 + nt * 8 + cc] =
                    make_float2(acc[nt][2], acc[nt][3]);
            }
            __syncthreads();
            // fused cell update -> h0(n+1)
            const float* xg = g_xg0 + (size_t)(n + 1) * GB + (size_t)blk * 128 * 32;
#pragma unroll
            for (int i = 0; i < 4; i++) {
                int q = tid + i * 256;
                int hh_l = q >> 5, b = q & 31, br = hh_l * 4;
                float f = sTile[br * 32 + b] + xg[br * 32 + b] + bf[i];
                float w = sTile[(br + 1) * 32 + b] + xg[(br + 1) * 32 + b] + bw[i];
                float i_ = sTile[(br + 2) * 32 + b] + xg[(br + 2) * 32 + b] + bi_[i];
                float o = sTile[(br + 3) * 32 + b] + xg[(br + 3) * 32 + b] + bo[i];
                float cv = sC[q];
                float cn = cv * sigf(f) + sigf(w) * tanhfast(i_);
                float hn = tanhfast(cn) * sigf(o);
                sC[q] = cn;
                store_h_split(g_B0hi[1 - p], g_B0lo[1 - p], b, blk * 32 + hh_l, hn);
            }
            __syncthreads();                   // protect sC/sTile before next step
        }
    } else {
        // ------------------------------ LAYER 1 ------------------------------
        int blk = bid - 32;                    // 0..63
        int tile = wrp & 3;
        int kh = (wrp >> 2) * 32;              // k16 half offset
        const uint4* A1 = (const uint4*)g_Ahi + 1 * MAT_U4 +
            (size_t)(blk * 4 + tile) * NK16 * 32;
        const uint4* A2 = (const uint4*)g_Ahi + 2 * MAT_U4 +
            (size_t)(blk * 4 + tile) * NK16 * 32;

        float bf[2], bw[2], bi_[2], bo[2];
#pragma unroll
        for (int i = 0; i < 2; i++) {
            int hh = blk * 16 + ((tid + i * 256) >> 5);
            bf[i] = Bias[4096 + hh]; bw[i] = Bias[5120 + hh];
            bi_[i] = Bias[6144 + hh]; bo[i] = Bias[7168 + hh];
        }
        sC[tid] = 0.0f;
        sC[tid + 256] = 0.0f;

        for (int n = 0; n < NT; n++) {
            grid_sync(gen);
            int p = n & 1;
            float acc[4][4];
#pragma unroll
            for (int nt = 0; nt < 4; nt++)
#pragma unroll
                for (int q = 0; q < 4; q++) acc[nt][q] = 0.0f;

            // phase 1: B = h1(n-1), A = Wh1
            {
                const uint4* srcH = (const uint4*)g_B1hi[p];
                const uint4* srcL = (const uint4*)g_B1lo[p];
#pragma unroll
                for (int i = 0; i < 16; i++) {
                    int idx = i * 256 + tid;
                    ((uint4*)sBhi)[idx] = srcH[idx];
                    ((uint4*)sBlo)[idx] = srcL[idx];
                }
            }
            __syncthreads();
#pragma unroll 8
            for (int kk = 0; kk < 32; kk++) {
                int k16 = kh + kk;
                uint4 ah = A1[k16 * 32 + lane];
#pragma unroll
                for (int nt = 0; nt < 4; nt++) {
                    int bix = ((k16 * 4 + nt) * 32 + lane) * 2;
                    mma_f16(acc[nt], ah, sBhi[bix], sBhi[bix + 1]);
                    mma_f16(acc[nt], ah, sBlo[bix], sBlo[bix + 1]);
                }
            }
            __syncthreads();
            // phase 2: B = h0(n), A = Wx1
            {
                const uint4* srcH = (const uint4*)g_B0hi[p];
                const uint4* srcL = (const uint4*)g_B0lo[p];
#pragma unroll
                for (int i = 0; i < 16; i++) {
                    int idx = i * 256 + tid;
                    ((uint4*)sBhi)[idx] = srcH[idx];
                    ((uint4*)sBlo)[idx] = srcL[idx];
                }
            }
            __syncthreads();
#pragma unroll 8
            for (int kk = 0; kk < 32; kk++) {
                int k16 = kh + kk;
                uint4 ah = A2[k16 * 32 + lane];
#pragma unroll
                for (int nt = 0; nt < 4; nt++) {
                    int bix = ((k16 * 4 + nt) * 32 + lane) * 2;
                    mma_f16(acc[nt], ah, sBhi[bix], sBhi[bix + 1]);
                    mma_f16(acc[nt], ah, sBlo[bix], sBlo[bix + 1]);
                }
            }
            // epilogue: two warp-sets combine in smem tile (64x32)
            int r0 = tile * 16 + (lane >> 2);
            int cc = (lane & 3) * 2;
            if (wrp < 4) {
#pragma unroll
                for (int nt = 0; nt < 4; nt++) {
                    *(float2*)&sTile[r0 * 32 + nt * 8 + cc] =
                        make_float2(acc[nt][0], acc[nt][1]);
                    *(float2*)&sTile[(r0 + 8) * 32 + nt * 8 + cc] =
                        make_float2(acc[nt][2], acc[nt][3]);
                }
            }
            __syncthreads();
            if (wrp >= 4) {
#pragma unroll
                for (int nt = 0; nt < 4; nt++) {
                    float2* p0 = (float2*)&sTile[r0 * 32 + nt * 8 + cc];
                    float2* p1 = (float2*)&sTile[(r0 + 8) * 32 + nt * 8 + cc];
                    float2 v0 = *p0, v1 = *p1;
                    v0.x += acc[nt][0]; v0.y += acc[nt][1];
                    v1.x += acc[nt][2]; v1.y += acc[nt][3];
                    *p0 = v0; *p1 = v1;
                }
            }
            __syncthreads();
            // fused cell update -> h1(n)
#pragma unroll
            for (int i = 0; i < 2; i++) {
                int q = tid + i * 256;
                int hh_l = q >> 5, b = q & 31, br = hh_l * 4;
                float f = sTile[br * 32 + b] + bf[i];
                float w = sTile[(br + 1) * 32 + b] + bw[i];
                float i_ = sTile[(br + 2) * 32 + b] + bi_[i];
                float o = sTile[(br + 3) * 32 + b] + bo[i];
                float cv = sC[q];
                float cn = cv * sigf(f) + sigf(w) * tanhfast(i_);
                float hn = tanhfast(cn) * sigf(o);
                sC[q] = cn;
                store_h_split(g_B1hi[1 - p], g_B1lo[1 - p], b, blk * 16 + hh_l, hn);
                if (n == NT - 1) out[b * 1024 + blk * 16 + hh_l] = hn;
            }
            __syncthreads();
        }
    }
}

// ---------------------------------------------------------------------------
extern "C" void kernel_launch(void* const* d_in, const int* in_sizes, int n_in,
                              void* d_out, int out_size) {
    const float* seq  = (const float*)d_in[0];  // (32, 512, 1024)
    const float* Wh   = (const float*)d_in[1];  // (2, 4, 1024, 1024)
    const float* Wx   = (const float*)d_in[2];  // (2, 4, 1024, 1024)
    const float* Bias = (const float*)d_in[3];  // (2, 4, 1024)
    float* out = (float*)d_out;                 // (32, 1024)

    cudaFuncSetAttribute(lstm_persist,
                         cudaFuncAttributeMaxDynamicSharedMemorySize, SMEM_BYTES);
    cudaFuncSetAttribute(pregemm_mma,
                         cudaFuncAttributeMaxDynamicSharedMemorySize, PRE_SMEM);

    init_state<<<64, 256>>>();
    prep_weights<<<4 * 4096 * 1024 / 256, 256>>>(Wh, Wx);
    prep_seq<<<NB * NT * NI / 256, 256>>>(seq);
    pregemm_mma<<<dim3(32, 128), 256, PRE_SMEM>>>();
    lstm_persist<<<GRID_BLOCKS, 256, SMEM_BYTES>>>(Bias, out);
}